// round 1
// baseline (speedup 1.0000x reference)
#include <cuda_runtime.h>
#include <math.h>

// DCN collapsed-affine implementation.
// Inputs (metadata order):
//  0 numb_features (4096,13) f32
//  1 cat_features  (4096,26) i32
//  2 emb_tables    (26,10000,64) f32
//  3 bn0 (4,1677)  4 w1 (1024,1677)  5 b1 (1024)  6 bn1 (4,1024)
//  7 w2 (512,1024) 8 b2 (512)        9 bn2 (4,512)
// 10 w3 (256,512) 11 b3 (256)       12 bn3 (4,256)
// 13 cross_w (3,1664) 14 cross_b (3) 15 pred_w (1,1920) 16 pred_b (1)
// Output: (4096,1) f32 sigmoid.

#define EPSF 1e-5f

constexpr int Bn   = 4096;
constexpr int Fn   = 26;
constexpr int Vn   = 10000;
constexpr int Dn   = 64;
constexpr int D0   = 1664;   // Fn*Dn
constexpr int NUMB = 13;
constexpr int INW  = 1677;   // D0 + NUMB
constexpr int H1   = 1024;
constexpr int H2   = 512;
constexpr int H3   = 256;

// Scratch (device globals: no allocation allowed)
__device__ float g_v3[H2];
__device__ float g_v2p[4][H1];     // partial sums over i-chunks (deterministic, no atomics)
__device__ float g_up[8][1792];    // partial sums for u (1677 padded to 1792)
__device__ float g_q[INW];         // a0 .* u
__device__ float g_s[5];           // {Scw0, Scw1, Scw2, Spwx, r_total}

__device__ __forceinline__ float warp_sum(float v) {
    #pragma unroll
    for (int o = 16; o; o >>= 1) v += __shfl_xor_sync(0xffffffffu, v, o);
    return v;
}

// ---------------------------------------------------------------------------
// v3[j] = sum_i w3[i,j] * (a3[i] * pw_h[i]),  j < 512.  One block of 512.
__global__ void k_v3(const float* __restrict__ w3, const float* __restrict__ bn3,
                     const float* __restrict__ pred_w) {
    __shared__ float t3[H3];
    int t = threadIdx.x;
    if (t < H3) {
        float a3 = bn3[t] * rsqrtf(bn3[3 * H3 + t] + EPSF);
        t3[t] = a3 * pred_w[D0 + t];
    }
    __syncthreads();
    float acc = 0.f;
    #pragma unroll 8
    for (int i = 0; i < H3; i++) acc += w3[i * H2 + t] * t3[i];
    g_v3[t] = acc;
}

// ---------------------------------------------------------------------------
// v2 partials: v2p[ib][j] = sum_{i in chunk ib} w2[i,j] * (a2[i]*v3[i]).
// grid = 32 (8 j-chunks x 4 i-chunks), block = 128.
__global__ void k_v2(const float* __restrict__ w2, const float* __restrict__ bn2) {
    int jb = blockIdx.x & 7, ib = blockIdx.x >> 3;
    int t  = threadIdx.x;
    int j  = jb * 128 + t;
    int i0 = ib * 128;
    __shared__ float t2[128];
    float a2 = bn2[i0 + t] * rsqrtf(bn2[3 * H2 + i0 + t] + EPSF);
    t2[t] = a2 * g_v3[i0 + t];
    __syncthreads();
    float acc = 0.f;
    #pragma unroll 8
    for (int i = 0; i < 128; i++) acc += w2[(i0 + i) * H1 + j] * t2[i];
    g_v2p[ib][j] = acc;
}

// ---------------------------------------------------------------------------
// u partials: up[ib][j] = sum_{i in chunk} w1[i,j] * (a1[i]*v2[i]),  j < 1677.
// grid = 112 (14 j-chunks x 8 i-chunks), block = 128.
__global__ void k_u(const float* __restrict__ w1, const float* __restrict__ bn1) {
    int jb = blockIdx.x % 14, ib = blockIdx.x / 14;
    int t  = threadIdx.x;
    int j  = jb * 128 + t;
    int i0 = ib * 128;
    __shared__ float t1[128];
    float v2 = g_v2p[0][i0 + t] + g_v2p[1][i0 + t] + g_v2p[2][i0 + t] + g_v2p[3][i0 + t];
    float a1 = bn1[i0 + t] * rsqrtf(bn1[3 * H1 + i0 + t] + EPSF);
    t1[t] = a1 * v2;
    __syncthreads();
    float acc = 0.f;
    if (j < INW) {
        #pragma unroll 8
        for (int i = 0; i < 128; i++) acc += w1[(size_t)(i0 + i) * INW + j] * t1[i];
    }
    g_up[ib][j] = acc;
}

// ---------------------------------------------------------------------------
// q[j] = a0[j]*u[j]; scalars: cross_w row sums, pw_x sum, and
// r = c0.u + d1.v2 + d2.v3 + d3.pw_h + pred_b.  One block of 1024.
__global__ void k_scalars(const float* __restrict__ bn0,
                          const float* __restrict__ b1, const float* __restrict__ bn1,
                          const float* __restrict__ b2, const float* __restrict__ bn2,
                          const float* __restrict__ b3, const float* __restrict__ bn3,
                          const float* __restrict__ cross_w,
                          const float* __restrict__ pred_w,
                          const float* __restrict__ pred_b) {
    int t = threadIdx.x;
    float r = 0.f, s0 = 0.f, s1 = 0.f, s2 = 0.f, sp = 0.f;

    for (int j = t; j < INW; j += 1024) {
        float u = 0.f;
        #pragma unroll
        for (int p = 0; p < 8; p++) u += g_up[p][j];
        float a0 = bn0[j] * rsqrtf(bn0[3 * INW + j] + EPSF);
        float c0 = bn0[INW + j] - bn0[2 * INW + j] * a0;
        g_q[j] = a0 * u;
        r += c0 * u;
    }
    {   // d1 . v2  (t covers 0..1023 exactly)
        int j = t;
        float v2 = g_v2p[0][j] + g_v2p[1][j] + g_v2p[2][j] + g_v2p[3][j];
        float a1 = bn1[j] * rsqrtf(bn1[3 * H1 + j] + EPSF);
        r += (a1 * b1[j] + bn1[H1 + j] - bn1[2 * H1 + j] * a1) * v2;
    }
    if (t < H2) {   // d2 . v3
        float a2 = bn2[t] * rsqrtf(bn2[3 * H2 + t] + EPSF);
        r += (a2 * b2[t] + bn2[H2 + t] - bn2[2 * H2 + t] * a2) * g_v3[t];
    }
    if (t < H3) {   // d3 . pw_h
        float a3 = bn3[t] * rsqrtf(bn3[3 * H3 + t] + EPSF);
        r += (a3 * b3[t] + bn3[H3 + t] - bn3[2 * H3 + t] * a3) * pred_w[D0 + t];
    }
    for (int j = t; j < D0; j += 1024) {
        s0 += cross_w[j];
        s1 += cross_w[D0 + j];
        s2 += cross_w[2 * D0 + j];
        sp += pred_w[j];
    }

    __shared__ float red[5][32];
    r  = warp_sum(r);  s0 = warp_sum(s0); s1 = warp_sum(s1);
    s2 = warp_sum(s2); sp = warp_sum(sp);
    int w = t >> 5, l = t & 31;
    if (l == 0) { red[0][w] = r; red[1][w] = s0; red[2][w] = s1; red[3][w] = s2; red[4][w] = sp; }
    __syncthreads();
    if (t < 32) {
        float a0v = warp_sum(red[0][t]);
        float a1v = warp_sum(red[1][t]);
        float a2v = warp_sum(red[2][t]);
        float a3v = warp_sum(red[3][t]);
        float a4v = warp_sum(red[4][t]);
        if (t == 0) {
            g_s[0] = a1v;              // Scw0 (unused downstream, kept for clarity)
            g_s[1] = a2v;              // Scw1
            g_s[2] = a3v;              // Scw2
            g_s[3] = a4v;              // Spwx
            g_s[4] = a0v + pred_b[0];  // r_total
        }
    }
}

// ---------------------------------------------------------------------------
// Main fused kernel: 1 warp per batch row.
// Gathers the 26 embedding rows and computes 5 dot products against vectors
// staged in shared memory, then the scalar cross-net chain + sigmoid.
__global__ __launch_bounds__(256) void k_main(
    const float* __restrict__ numb, const int* __restrict__ cat,
    const float* __restrict__ emb,  const float* __restrict__ cross_w,
    const float* __restrict__ cross_b, const float* __restrict__ pred_w,
    float* __restrict__ out) {

    __shared__ float sv[5][D0];   // cw0, cw1, cw2, pw_x, q_x

    for (int k = threadIdx.x; k < D0; k += 256) {
        sv[0][k] = cross_w[k];
        sv[1][k] = cross_w[D0 + k];
        sv[2][k] = cross_w[2 * D0 + k];
        sv[3][k] = pred_w[k];
        sv[4][k] = g_q[k];
    }
    __syncthreads();

    int warp = threadIdx.x >> 5;
    int lane = threadIdx.x & 31;
    int row  = blockIdx.x * 8 + warp;

    int myidx = (lane < Fn) ? cat[row * Fn + lane] : 0;

    float acc0 = 0.f, acc1 = 0.f, acc2 = 0.f, acc3 = 0.f, acc4 = 0.f;

    #pragma unroll
    for (int f = 0; f < Fn; f++) {
        int idx = __shfl_sync(0xffffffffu, myidx, f);
        const float2* src = reinterpret_cast<const float2*>(
            emb + (size_t)f * (Vn * Dn) + (size_t)idx * Dn);
        float2 e = src[lane];            // 64 floats / 32 lanes
        int b = f * Dn + lane * 2;
        acc0 += e.x * sv[0][b] + e.y * sv[0][b + 1];
        acc1 += e.x * sv[1][b] + e.y * sv[1][b + 1];
        acc2 += e.x * sv[2][b] + e.y * sv[2][b + 1];
        acc3 += e.x * sv[3][b] + e.y * sv[3][b + 1];
        acc4 += e.x * sv[4][b] + e.y * sv[4][b + 1];
    }
    if (lane < NUMB) acc4 += numb[row * NUMB + lane] * g_q[D0 + lane];

    acc0 = warp_sum(acc0);
    acc1 = warp_sum(acc1);
    acc2 = warp_sum(acc2);
    acc3 = warp_sum(acc3);
    acc4 = warp_sum(acc4);

    if (lane == 0) {
        float cb0 = cross_b[0], cb1 = cross_b[1], cb2 = cross_b[2];
        float Sc1 = g_s[1], Sc2 = g_s[2], Sp = g_s[3], rtot = g_s[4];

        // x1 = (s0+1) x0 + cb0
        float al = acc0 + 1.f;
        float be = cb0;
        // s1 = x1 . cw1
        float sd1 = al * acc1 + be * Sc1;
        al = (sd1 + 1.f) * al;
        be = (sd1 + 1.f) * be + cb1;
        // s2 = x2 . cw2
        float sd2 = al * acc2 + be * Sc2;
        al = (sd2 + 1.f) * al;
        be = (sd2 + 1.f) * be + cb2;

        float z = al * acc3 + be * Sp + acc4 + rtot;
        out[row] = 1.f / (1.f + expf(-z));
    }
}

// ---------------------------------------------------------------------------
extern "C" void kernel_launch(void* const* d_in, const int* in_sizes, int n_in,
                              void* d_out, int out_size) {
    const float* numb    = (const float*)d_in[0];
    const int*   cat     = (const int*)  d_in[1];
    const float* emb     = (const float*)d_in[2];
    const float* bn0     = (const float*)d_in[3];
    const float* w1      = (const float*)d_in[4];
    const float* b1      = (const float*)d_in[5];
    const float* bn1     = (const float*)d_in[6];
    const float* w2      = (const float*)d_in[7];
    const float* b2      = (const float*)d_in[8];
    const float* bn2     = (const float*)d_in[9];
    const float* w3      = (const float*)d_in[10];
    const float* b3      = (const float*)d_in[11];
    const float* bn3     = (const float*)d_in[12];
    const float* cross_w = (const float*)d_in[13];
    const float* cross_b = (const float*)d_in[14];
    const float* pred_w  = (const float*)d_in[15];
    const float* pred_b  = (const float*)d_in[16];
    float* out = (float*)d_out;

    k_v3<<<1, 512>>>(w3, bn3, pred_w);
    k_v2<<<32, 128>>>(w2, bn2);
    k_u<<<112, 128>>>(w1, bn1);
    k_scalars<<<1, 1024>>>(bn0, b1, bn1, b2, bn2, b3, bn3, cross_w, pred_w, pred_b);
    k_main<<<Bn / 8, 256>>>(numb, cat, emb, cross_w, cross_b, pred_w, out);
}

// round 2
// speedup vs baseline: 1.3944x; 1.3944x over previous
#include <cuda_runtime.h>
#include <math.h>

// DCN collapsed-affine implementation, round 2: parallelized precompute chain.
//
// Math: the whole network after the embedding gather is affine in x0 with
// per-row scalar corrections from the cross layers. Per row we need only
// 5 dot products of x0 (1664 floats) against fixed vectors:
//   cw0, cw1, cw2 (cross), pw_x (pred head), q = a0 .* W1^T a1 W2^T a2 W3^T (a3.*pw_h)
// plus numb . q_n and a scalar r collecting all bias/BN-shift terms.

#define EPSF 1e-5f

constexpr int Bn   = 4096;
constexpr int Fn   = 26;
constexpr int Vn   = 10000;
constexpr int Dn   = 64;
constexpr int D0   = 1664;   // Fn*Dn
constexpr int NUMB = 13;
constexpr int INW  = 1677;   // D0 + NUMB
constexpr int H1   = 1024;
constexpr int H2   = 512;
constexpr int H3   = 256;

// Scratch (device globals: no allocation allowed)
__device__ float g_v3p[8][H2];     // v3 partials over i-chunks
__device__ float g_v2p[8][H1];     // v2 partials
__device__ float g_up[16][1792];   // u partials (1677 padded to 1792)
__device__ float g_q[1792];        // a0 .* u
__device__ float g_r[1];           // scalar r (atomic accumulated)

__device__ __forceinline__ float warp_sum(float v) {
    #pragma unroll
    for (int o = 16; o; o >>= 1) v += __shfl_xor_sync(0xffffffffu, v, o);
    return v;
}

// ---------------------------------------------------------------------------
// v3 partials: grid 16 (2 j-chunks x 8 i-chunks), block 256.
// v3p[ib][j] = sum_{i in chunk} w3[i,j] * (a3[i]*pw_h[i])
__global__ void k_v3(const float* __restrict__ w3, const float* __restrict__ bn3,
                     const float* __restrict__ pred_w) {
    int bid = blockIdx.x;
    int ib = bid >> 1, jb = bid & 1;
    int t = threadIdx.x;
    int j = jb * 256 + t;
    int i0 = ib * 32;
    __shared__ float t3[32];
    if (t < 32) {
        int i = i0 + t;
        float a3 = bn3[i] * rsqrtf(bn3[3 * H3 + i] + EPSF);
        t3[t] = a3 * pred_w[D0 + i];
    }
    if (bid == 0 && t == 0) g_r[0] = 0.f;
    __syncthreads();
    float acc = 0.f;
    #pragma unroll
    for (int i = 0; i < 32; i++) acc += w3[(i0 + i) * H2 + j] * t3[i];
    g_v3p[ib][j] = acc;
}

// ---------------------------------------------------------------------------
// v2 partials: grid 64 (8 j-chunks x 8 i-chunks), block 128.
__global__ void k_v2(const float* __restrict__ w2, const float* __restrict__ bn2) {
    int bid = blockIdx.x;
    int jb = bid & 7, ib = bid >> 3;
    int t = threadIdx.x;
    int j = jb * 128 + t;
    int i0 = ib * 64;
    __shared__ float t2[64];
    if (t < 64) {
        int i = i0 + t;
        float v3 = 0.f;
        #pragma unroll
        for (int p = 0; p < 8; p++) v3 += g_v3p[p][i];
        float a2 = bn2[i] * rsqrtf(bn2[3 * H2 + i] + EPSF);
        t2[t] = a2 * v3;
    }
    __syncthreads();
    float acc = 0.f;
    #pragma unroll 8
    for (int i = 0; i < 64; i++) acc += w2[(i0 + i) * H1 + j] * t2[i];
    g_v2p[ib][j] = acc;
}

// ---------------------------------------------------------------------------
// u partials: grid 224 (14 j-chunks x 16 i-chunks), block 128.
__global__ void k_u(const float* __restrict__ w1, const float* __restrict__ bn1) {
    int bid = blockIdx.x;
    int jb = bid % 14, ib = bid / 14;
    int t = threadIdx.x;
    int j = jb * 128 + t;
    int i0 = ib * 64;
    __shared__ float t1[64];
    if (t < 64) {
        int i = i0 + t;
        float v2 = 0.f;
        #pragma unroll
        for (int p = 0; p < 8; p++) v2 += g_v2p[p][i];
        float a1 = bn1[i] * rsqrtf(bn1[3 * H1 + i] + EPSF);
        t1[t] = a1 * v2;
    }
    __syncthreads();
    float acc = 0.f;
    if (j < INW) {
        #pragma unroll 8
        for (int i = 0; i < 64; i++)
            acc += w1[(size_t)(i0 + i) * INW + j] * t1[i];
    }
    g_up[ib][j] = acc;
}

// ---------------------------------------------------------------------------
// q[j] = a0[j]*u[j]; r = c0.u + d1.v2 + d2.v3 + d3.pw_h + pred_b.
// grid 14, block 128; r accumulated via one atomicAdd per block.
__global__ void k_scalars(const float* __restrict__ bn0,
                          const float* __restrict__ b1, const float* __restrict__ bn1,
                          const float* __restrict__ b2, const float* __restrict__ bn2,
                          const float* __restrict__ b3, const float* __restrict__ bn3,
                          const float* __restrict__ pred_w,
                          const float* __restrict__ pred_b) {
    int t = threadIdx.x;
    int j = blockIdx.x * 128 + t;
    float r = 0.f;

    if (j < INW) {
        float u = 0.f;
        #pragma unroll
        for (int p = 0; p < 16; p++) u += g_up[p][j];
        float a0 = bn0[j] * rsqrtf(bn0[3 * INW + j] + EPSF);
        float c0 = bn0[INW + j] - bn0[2 * INW + j] * a0;
        g_q[j] = a0 * u;
        r += c0 * u;
    }
    if (j < H1) {
        float v2 = 0.f;
        #pragma unroll
        for (int p = 0; p < 8; p++) v2 += g_v2p[p][j];
        float a1 = bn1[j] * rsqrtf(bn1[3 * H1 + j] + EPSF);
        r += (a1 * b1[j] + bn1[H1 + j] - bn1[2 * H1 + j] * a1) * v2;
    }
    if (j < H2) {
        float v3 = 0.f;
        #pragma unroll
        for (int p = 0; p < 8; p++) v3 += g_v3p[p][j];
        float a2 = bn2[j] * rsqrtf(bn2[3 * H2 + j] + EPSF);
        r += (a2 * b2[j] + bn2[H2 + j] - bn2[2 * H2 + j] * a2) * v3;
    }
    if (j < H3) {
        float a3 = bn3[j] * rsqrtf(bn3[3 * H3 + j] + EPSF);
        r += (a3 * b3[j] + bn3[H3 + j] - bn3[2 * H3 + j] * a3) * pred_w[D0 + j];
    }
    if (j == 0) r += pred_b[0];

    __shared__ float red[4];
    r = warp_sum(r);
    if ((t & 31) == 0) red[t >> 5] = r;
    __syncthreads();
    if (t == 0) {
        float rb = red[0] + red[1] + red[2] + red[3];
        atomicAdd(&g_r[0], rb);
    }
}

// ---------------------------------------------------------------------------
// Main fused kernel: 1024 threads/block, 32 warps, 1 warp per batch row.
// Prologue stages the 5 vectors into smem and computes Sc1/Sc2/Sp for free.
__global__ __launch_bounds__(1024) void k_main(
    const float* __restrict__ numb, const int* __restrict__ cat,
    const float* __restrict__ emb,  const float* __restrict__ cross_w,
    const float* __restrict__ cross_b, const float* __restrict__ pred_w,
    float* __restrict__ out) {

    __shared__ float sv[5][D0];   // cw0, cw1, cw2, pw_x, q_x
    __shared__ float s_qn[16];    // q over numb features
    __shared__ float red[3][32];
    __shared__ float s_sc[4];     // Sc1, Sc2, Sp, r

    int tid = threadIdx.x;
    float p1 = 0.f, p2 = 0.f, p3 = 0.f;
    for (int k = tid; k < D0; k += 1024) {
        float c0 = cross_w[k];
        float c1 = cross_w[D0 + k];
        float c2 = cross_w[2 * D0 + k];
        float pw = pred_w[k];
        sv[0][k] = c0; sv[1][k] = c1; sv[2][k] = c2; sv[3][k] = pw;
        sv[4][k] = g_q[k];
        p1 += c1; p2 += c2; p3 += pw;
    }
    if (tid < NUMB) s_qn[tid] = g_q[D0 + tid];

    p1 = warp_sum(p1); p2 = warp_sum(p2); p3 = warp_sum(p3);
    int warp = tid >> 5, lane = tid & 31;
    if (lane == 0) { red[0][warp] = p1; red[1][warp] = p2; red[2][warp] = p3; }
    __syncthreads();
    if (tid < 32) {
        float a = warp_sum(red[0][tid]);
        float b = warp_sum(red[1][tid]);
        float c = warp_sum(red[2][tid]);
        if (tid == 0) { s_sc[0] = a; s_sc[1] = b; s_sc[2] = c; s_sc[3] = g_r[0]; }
    }
    __syncthreads();

    int row = blockIdx.x * 32 + warp;
    int myidx = (lane < Fn) ? cat[row * Fn + lane] : 0;

    float acc0 = 0.f, acc1 = 0.f, acc2 = 0.f, acc3 = 0.f, acc4 = 0.f;

    #pragma unroll
    for (int f = 0; f < Fn; f++) {
        int idx = __shfl_sync(0xffffffffu, myidx, f);
        const float2* src = reinterpret_cast<const float2*>(
            emb + (size_t)f * (Vn * Dn) + (size_t)idx * Dn);
        float2 e = src[lane];            // 64 floats / 32 lanes
        int b = f * Dn + lane * 2;
        acc0 += e.x * sv[0][b] + e.y * sv[0][b + 1];
        acc1 += e.x * sv[1][b] + e.y * sv[1][b + 1];
        acc2 += e.x * sv[2][b] + e.y * sv[2][b + 1];
        acc3 += e.x * sv[3][b] + e.y * sv[3][b + 1];
        acc4 += e.x * sv[4][b] + e.y * sv[4][b + 1];
    }
    if (lane < NUMB) acc4 += numb[row * NUMB + lane] * s_qn[lane];

    acc0 = warp_sum(acc0);
    acc1 = warp_sum(acc1);
    acc2 = warp_sum(acc2);
    acc3 = warp_sum(acc3);
    acc4 = warp_sum(acc4);

    if (lane == 0) {
        float cb0 = cross_b[0], cb1 = cross_b[1], cb2 = cross_b[2];
        float Sc1 = s_sc[0], Sc2 = s_sc[1], Sp = s_sc[2], rtot = s_sc[3];

        // x1 = (s0+1) x0 + cb0
        float al = acc0 + 1.f;
        float be = cb0;
        // s1 = x1 . cw1
        float sd1 = al * acc1 + be * Sc1;
        al = (sd1 + 1.f) * al;
        be = (sd1 + 1.f) * be + cb1;
        // s2 = x2 . cw2
        float sd2 = al * acc2 + be * Sc2;
        al = (sd2 + 1.f) * al;
        be = (sd2 + 1.f) * be + cb2;

        float z = al * acc3 + be * Sp + acc4 + rtot;
        out[row] = 1.f / (1.f + expf(-z));
    }
}

// ---------------------------------------------------------------------------
extern "C" void kernel_launch(void* const* d_in, const int* in_sizes, int n_in,
                              void* d_out, int out_size) {
    const float* numb    = (const float*)d_in[0];
    const int*   cat     = (const int*)  d_in[1];
    const float* emb     = (const float*)d_in[2];
    const float* bn0     = (const float*)d_in[3];
    const float* w1      = (const float*)d_in[4];
    const float* b1      = (const float*)d_in[5];
    const float* bn1     = (const float*)d_in[6];
    const float* w2      = (const float*)d_in[7];
    const float* b2      = (const float*)d_in[8];
    const float* bn2     = (const float*)d_in[9];
    const float* w3      = (const float*)d_in[10];
    const float* b3      = (const float*)d_in[11];
    const float* bn3     = (const float*)d_in[12];
    const float* cross_w = (const float*)d_in[13];
    const float* cross_b = (const float*)d_in[14];
    const float* pred_w  = (const float*)d_in[15];
    const float* pred_b  = (const float*)d_in[16];
    float* out = (float*)d_out;

    k_v3<<<16, 256>>>(w3, bn3, pred_w);
    k_v2<<<64, 128>>>(w2, bn2);
    k_u<<<224, 128>>>(w1, bn1);
    k_scalars<<<14, 128>>>(bn0, b1, bn1, b2, bn2, b3, bn3, pred_w, pred_b);
    k_main<<<Bn / 32, 1024>>>(numb, cat, emb, cross_w, cross_b, pred_w, out);
}